// round 17
// baseline (speedup 1.0000x reference)
#include <cuda_runtime.h>
#include <cstdint>

// ---------------------------------------------------------------------------
// fp4 (bitsandbytes) dequant + GEMV:  y[4, M] = x[4, N] @ W[M, N]^T + bias
//   qweight: numel/2 int32, each holding ONE byte (two nibbles, hi first)
//   absmax : per-64-element block scale; code: 16-entry codebook
//
// R17: ALL streaming through a block-level cp.async.bulk ring (async proxy,
// no register scoreboard). Ring of DEPTH=2 stages; each stage = 16 q rows
// x 512B + 4 x-batch rows x 1KB (12 KB), completed on an mbarrier
// (expect_tx). Consumers read only smem: q = LDS.32 conflict-free,
// x = LDS.64 conflict-free, absmax = smem table, decode = register-SHFL
// codebook, packed f32x2 FMAs. __syncthreads after each stage gates slot
// reuse; tid0 refills. 28 KB smem -> 8 CTAs/SM, 32 warps, grid (2,512)
// = 1024 blocks in ONE wave. Epilogue: cudaMemsetAsync zero + exactly two
// commutative atomicAdds per output (bit-deterministic), bias in split 0.
// ---------------------------------------------------------------------------

constexpr int MD = 8192, ND = 8192;
constexpr int NSPLIT = 2;
constexpr int NHALF  = ND / NSPLIT;     // 4096 n per block
constexpr int CHALF  = NHALF / 2;       // 2048 int32 per row-half
constexpr int RW = 4;                   // rows per warp
constexpr int WPB = 4;                  // warps per block (128 threads)
constexpr int RPB = RW * WPB;           // 16 rows per block
constexpr int SW   = 128;               // int32 cols per stage (256 n)
constexpr int NSTG = CHALF / SW;        // 16 stages
constexpr int DEPTH = 2;                // ring slots
constexpr int SPT  = SW / 32;           // 4 steps per stage
constexpr int STEPS = NSTG * SPT;       // 64 steps of 64 n
constexpr unsigned STAGE_TX = RPB * SW * 4 + 4 * SW * 2 * 4;   // 8192+4096

static __device__ __forceinline__ unsigned long long pk2(float lo, float hi) {
    unsigned long long r;
    asm("mov.b64 %0, {%1, %2};" : "=l"(r) : "f"(lo), "f"(hi));
    return r;
}
static __device__ __forceinline__ void up2(unsigned long long v, float& lo, float& hi) {
    asm("mov.b64 {%0, %1}, %2;" : "=f"(lo), "=f"(hi) : "l"(v));
}
static __device__ __forceinline__ unsigned long long f2fma(unsigned long long a,
                                                           unsigned long long b,
                                                           unsigned long long c) {
    unsigned long long d;
    asm("fma.rn.f32x2 %0, %1, %2, %3;" : "=l"(d) : "l"(a), "l"(b), "l"(c));
    return d;
}
static __device__ __forceinline__ unsigned long long f2add(unsigned long long a,
                                                           unsigned long long b) {
    unsigned long long d;
    asm("add.rn.f32x2 %0, %1, %2;" : "=l"(d) : "l"(a), "l"(b));
    return d;
}
static __device__ __forceinline__ uint32_t s2u(const void* p) {
    uint32_t a;
    asm("{.reg .u64 t; cvta.to.shared.u64 t, %1; cvt.u32.u64 %0, t;}" : "=r"(a) : "l"(p));
    return a;
}
static __device__ __forceinline__ void bulk_cp(uint32_t dst, const void* src,
                                               uint32_t bytes, uint32_t mbar) {
    asm volatile(
        "cp.async.bulk.shared::cluster.global.mbarrier::complete_tx::bytes "
        "[%0], [%1], %2, [%3];"
        :: "r"(dst), "l"(src), "r"(bytes), "r"(mbar) : "memory");
}
static __device__ __forceinline__ void mbar_wait(uint32_t mb, uint32_t parity) {
    uint32_t done;
    asm volatile(
        "{\n\t.reg .pred p;\n\t"
        "mbarrier.try_wait.parity.acquire.cta.shared::cta.b64 p, [%1], %2;\n\t"
        "selp.b32 %0, 1, 0, p;\n\t}"
        : "=r"(done) : "r"(mb), "r"(parity) : "memory");
    if (!done) {
        asm volatile(
            "{\n\t.reg .pred P1;\n\t"
            "W0_%=:\n\t"
            "mbarrier.try_wait.parity.acquire.cta.shared::cta.b64 P1, [%0], %1, 0x989680;\n\t"
            "@P1 bra.uni WD_%=;\n\t"
            "bra.uni W0_%=;\n\t"
            "WD_%=:\n\t}"
            :: "r"(mb), "r"(parity) : "memory");
    }
}

// tid0-only: set expect_tx then issue all 20 bulk copies for stage s.
static __device__ __forceinline__ void issue_stage(
    int s, uint32_t mb, uint32_t q_dst0, uint32_t x_dst0,
    const int* __restrict__ qbase, const float* __restrict__ xbase)
{
    asm volatile("mbarrier.arrive.expect_tx.shared.b64 _, [%0], %1;"
                 :: "r"(mb), "r"(STAGE_TX) : "memory");
    const int* qs = qbase + s * SW;
#pragma unroll
    for (int r = 0; r < RPB; r++)
        bulk_cp(q_dst0 + (uint32_t)(r * SW * 4), qs + r * (ND / 2), SW * 4, mb);
    const float* xs = xbase + s * (SW * 2);
#pragma unroll
    for (int b = 0; b < 4; b++)
        bulk_cp(x_dst0 + (uint32_t)(b * SW * 2 * 4), xs + b * ND, SW * 2 * 4, mb);
}

__global__ void __launch_bounds__(128, 8)
fp4_main(const float* __restrict__ x, const int* __restrict__ qw,
         const float* __restrict__ am, const float* __restrict__ code,
         const float* __restrict__ bias, float* __restrict__ out)
{
    __shared__ __align__(128) int   q_sm[DEPTH][RPB][SW];     // 16 KB
    __shared__ __align__(128) float x_sm[DEPTH][4][SW * 2];   // 8 KB
    __shared__ float am_sm[RPB * 64];                          // 4 KB
    __shared__ __align__(8) unsigned long long mbar_sm[DEPTH];

    const int tid  = threadIdx.x;
    const int lane = tid & 31;
    const int wid  = tid >> 5;
    const int split   = blockIdx.x;            // 0 or 1
    const int rowbase = blockIdx.y * RPB;
    const int row0    = rowbase + wid * RW;
    const int n0      = split * NHALF;

    // Register-resident codebook: lane l holds code[l & 15]; decode via shfl.
    const float creg = code[lane & 15];

    // smem addresses
    const uint32_t mb0 = s2u(&mbar_sm[0]);
    const uint32_t mb1 = s2u(&mbar_sm[1]);
    const uint32_t qd0 = s2u(&q_sm[0][0][0]);
    const uint32_t qd1 = s2u(&q_sm[1][0][0]);
    const uint32_t xd0 = s2u(&x_sm[0][0][0]);
    const uint32_t xd1 = s2u(&x_sm[1][0][0]);

    if (tid == 0) {
        asm volatile("mbarrier.init.shared.b64 [%0], 1;" :: "r"(mb0) : "memory");
        asm volatile("mbarrier.init.shared.b64 [%0], 1;" :: "r"(mb1) : "memory");
    }

    // absmax preload: [row-in-block][block 0..63], coalesced.
    for (int k = tid; k < RPB * 64; k += 128) {
        const int r  = k >> 6;
        const int bl = k & 63;
        am_sm[k] = am[(rowbase + r) * (ND / 64) + split * (NHALF / 64) + bl];
    }
    __syncthreads();   // mbarriers + am_sm visible

    const int*   qbase = qw + rowbase * (ND / 2) + split * CHALF;
    const float* xbase = x + n0;

    // Prologue: fill both ring slots.
    if (tid == 0) {
        issue_stage(0, mb0, qd0, xd0, qbase, xbase);
        issue_stage(1, mb1, qd1, xd1, qbase, xbase);
    }

    unsigned long long a01[RW] = {0, 0, 0, 0};
    unsigned long long a23[RW] = {0, 0, 0, 0};

    for (int s = 0; s < NSTG; ++s) {
        const int slot = s & 1;
        const uint32_t mb = slot ? mb1 : mb0;
        mbar_wait(mb, (s >> 1) & 1);

#pragma unroll
        for (int t = 0; t < SPT; ++t) {
            const int step = s * SPT + t;
            const int colL = t * 32 + lane;            // 0..127 within stage

            // x pairs for this lane's two n, all 4 batches. LDS.64 conflict-free.
            const float2 v0 = *reinterpret_cast<const float2*>(&x_sm[slot][0][2 * colL]);
            const float2 v1 = *reinterpret_cast<const float2*>(&x_sm[slot][1][2 * colL]);
            const float2 v2 = *reinterpret_cast<const float2*>(&x_sm[slot][2][2 * colL]);
            const float2 v3 = *reinterpret_cast<const float2*>(&x_sm[slot][3][2 * colL]);
            const unsigned long long xe01 = pk2(v0.x, v1.x);
            const unsigned long long xo01 = pk2(v0.y, v1.y);
            const unsigned long long xe23 = pk2(v2.x, v3.x);
            const unsigned long long xo23 = pk2(v2.y, v3.y);

#pragma unroll
            for (int r = 0; r < RW; r++) {
                const int   b = q_sm[slot][wid * RW + r][colL];       // LDS.32
                const float sc = am_sm[(wid * RW + r) * 64 + step];   // uniform
                const float chi = __shfl_sync(0xffffffffu, creg, b >> 4);
                const float clo = __shfl_sync(0xffffffffu, creg, b & 15);
                const float w0 = chi * sc;
                const float w1 = clo * sc;
                const unsigned long long s0 = pk2(w0, w0);
                const unsigned long long s1 = pk2(w1, w1);
                a01[r] = f2fma(s0, xe01, a01[r]);
                a01[r] = f2fma(s1, xo01, a01[r]);
                a23[r] = f2fma(s0, xe23, a23[r]);
                a23[r] = f2fma(s1, xo23, a23[r]);
            }
        }

        __syncthreads();   // whole block done with this slot
        if (tid == 0 && s + DEPTH < NSTG) {
            issue_stage(s + DEPTH, mb, (slot ? qd1 : qd0), (slot ? xd1 : xd0),
                        qbase, xbase);
        }
    }

    // Butterfly reduction over lanes (packed f32x2 adds).
#pragma unroll
    for (int r = 0; r < RW; r++) {
#pragma unroll
        for (int off = 16; off > 0; off >>= 1) {
            a01[r] = f2add(a01[r], __shfl_xor_sync(0xffffffffu, a01[r], off));
            a23[r] = f2add(a23[r], __shfl_xor_sync(0xffffffffu, a23[r], off));
        }
    }

    // out was zeroed by the memset node. Exactly two commutative IEEE adds
    // per output -> bit-deterministic. Bias contributed once (split 0).
#pragma unroll
    for (int r = 0; r < RW; r++) {
        if (lane == r) {
            const int row = row0 + r;
            float y0, y1, y2, y3;
            up2(a01[r], y0, y1);
            up2(a23[r], y2, y3);
            if (split == 0) {
                const float bb = bias[row];
                y0 += bb; y1 += bb; y2 += bb; y3 += bb;
            }
            atomicAdd(&out[0 * MD + row], y0);
            atomicAdd(&out[1 * MD + row], y1);
            atomicAdd(&out[2 * MD + row], y2);
            atomicAdd(&out[3 * MD + row], y3);
        }
    }
}

extern "C" void kernel_launch(void* const* d_in, const int* in_sizes, int n_in,
                              void* d_out, int out_size)
{
    const float* x    = (const float*)d_in[0];
    const int*   qw   = (const int*)d_in[1];
    const float* am   = (const float*)d_in[2];
    const float* code = (const float*)d_in[3];
    const float* bias = (const float*)d_in[4];
    float*       out  = (float*)d_out;

    cudaMemsetAsync(out, 0, (size_t)out_size * sizeof(float));
    dim3 grid(NSPLIT, MD / RPB);              // (2, 512) = 1024 blocks
    fp4_main<<<grid, WPB * 32>>>(x, qw, am, code, bias, out);
}